// round 1
// baseline (speedup 1.0000x reference)
#include <cuda_runtime.h>
#include <math_constants.h>

#define NE 100000
#define NR 1000
#define EC 1000000
#define HID 128
#define OUTD 256

// ---- scratch (device globals: allocation-free) ----
__device__ float g_eh[NE];
__device__ float g_et[NE];
__device__ float g_er[NR];
__device__ float g_maxh[NE];
__device__ float g_maxt[NE];
__device__ float g_sumh[NE];
__device__ float g_sumt[NE];
__device__ float g_lh[EC];
__device__ float g_lt[EC];
__device__ float g_msg[NR * HID];
__device__ float g_mWh[NR * OUTD];
__device__ float g_mWt[NR * OUTD];

__device__ __forceinline__ void atomicMaxF(float* addr, float v) {
    if (v >= 0.0f) atomicMax((int*)addr, __float_as_int(v));
    else           atomicMin((unsigned int*)addr, __float_as_uint(v));
}

// ---- init segment max/sum ----
__global__ void k_init_nodes() {
    int i = blockIdx.x * blockDim.x + threadIdx.x;
    if (i < NE) {
        g_maxh[i] = -CUDART_INF_F;
        g_maxt[i] = -CUDART_INF_F;
        g_sumh[i] = 0.0f;
        g_sumt[i] = 0.0f;
    }
}

// ---- init out rows to bias ----
__global__ void k_init_out(float* __restrict__ out, const float* __restrict__ br) {
    out[(size_t)blockIdx.x * OUTD + threadIdx.x] = br[threadIdx.x];
}

// ---- per-entity attention scores: warp per node ----
__global__ void k_node_scores(const float* __restrict__ xe,
                              const float* __restrict__ wah,
                              const float* __restrict__ wat) {
    int warp = (blockIdx.x * blockDim.x + threadIdx.x) >> 5;
    int lane = threadIdx.x & 31;
    if (warp >= NE) return;
    const float4* row = (const float4*)(xe + (size_t)warp * HID);
    float4 v = row[lane];
    float4 a = ((const float4*)wah)[lane];
    float4 b = ((const float4*)wat)[lane];
    float sh = v.x * a.x + v.y * a.y + v.z * a.z + v.w * a.w;
    float st = v.x * b.x + v.y * b.y + v.z * b.z + v.w * b.w;
    #pragma unroll
    for (int o = 16; o; o >>= 1) {
        sh += __shfl_xor_sync(0xFFFFFFFFu, sh, o);
        st += __shfl_xor_sync(0xFFFFFFFFu, st, o);
    }
    if (lane == 0) { g_eh[warp] = sh; g_et[warp] = st; }
}

// ---- per-relation attention scores: warp per relation ----
__global__ void k_rel_scores(const float* __restrict__ xr,
                             const float* __restrict__ war) {
    int warp = (blockIdx.x * blockDim.x + threadIdx.x) >> 5;
    int lane = threadIdx.x & 31;
    if (warp >= NR) return;
    const float4* row = (const float4*)(xr + (size_t)warp * HID);
    float4 v = row[lane];
    float4 a = ((const float4*)war)[lane];
    float s = v.x * a.x + v.y * a.y + v.z * a.z + v.w * a.w;
    #pragma unroll
    for (int o = 16; o; o >>= 1) s += __shfl_xor_sync(0xFFFFFFFFu, s, o);
    if (lane == 0) g_er[warp] = s;
}

// ---- relation message MLP: msg = x_r + (x_r@W1+b1)@W2+b2 ; block per relation ----
__global__ void k_msg(const float* __restrict__ xr,
                      const float* __restrict__ W1, const float* __restrict__ b1,
                      const float* __restrict__ W2, const float* __restrict__ b2) {
    __shared__ float xs[HID];
    __shared__ float hs[2 * HID];
    int r = blockIdx.x, tid = threadIdx.x;
    if (tid < HID) xs[tid] = xr[(size_t)r * HID + tid];
    __syncthreads();
    float acc = b1[tid];
    #pragma unroll 8
    for (int k = 0; k < HID; k++) acc += xs[k] * W1[k * 256 + tid];
    hs[tid] = acc;
    __syncthreads();
    if (tid < HID) {
        float o = b2[tid];
        #pragma unroll 8
        for (int j = 0; j < 256; j++) o += hs[j] * W2[j * HID + tid];
        g_msg[(size_t)r * HID + tid] = xs[tid] + o;
    }
}

// ---- fold output projection into message tables: block per relation ----
__global__ void k_msgW(const float* __restrict__ Wr) {
    __shared__ float ms[HID];
    int r = blockIdx.x, c = threadIdx.x;
    if (c < HID) ms[c] = g_msg[(size_t)r * HID + c];
    __syncthreads();
    float ah = 0.0f, at = 0.0f;
    #pragma unroll 8
    for (int k = 0; k < HID; k++) {
        float m = ms[k];
        ah += m * Wr[k * 256 + c];
        at += m * Wr[(k + HID) * 256 + c];
    }
    g_mWh[(size_t)r * 256 + c] = ah;
    g_mWt[(size_t)r * 256 + c] = at;
}

// ---- edge pass 1: logits + segment max ----
__global__ void k_logits(const int* __restrict__ ei, const int* __restrict__ rel) {
    int e = blockIdx.x * blockDim.x + threadIdx.x;
    if (e >= EC) return;
    int h = ei[e], t = ei[EC + e], r = rel[e];
    float er = g_er[r];
    float lh = g_eh[h] + er;
    lh = lh > 0.0f ? lh : 0.01f * lh;
    float lt = g_et[t] + er;
    lt = lt > 0.0f ? lt : 0.01f * lt;
    g_lh[e] = lh;
    g_lt[e] = lt;
    atomicMaxF(&g_maxh[h], lh);
    atomicMaxF(&g_maxt[t], lt);
}

// ---- edge pass 2: segment sums of exp(l - max) ----
__global__ void k_sums(const int* __restrict__ ei) {
    int e = blockIdx.x * blockDim.x + threadIdx.x;
    if (e >= EC) return;
    int h = ei[e], t = ei[EC + e];
    atomicAdd(&g_sumh[h], __expf(g_lh[e] - g_maxh[h]));
    atomicAdd(&g_sumt[t], __expf(g_lt[e] - g_maxt[t]));
}

// ---- edge pass 3: weighted scatter into out; warp per edge, float4 RED ----
__global__ void k_scatter(const int* __restrict__ ei, const int* __restrict__ rel,
                          float* __restrict__ out) {
    int e = (blockIdx.x * blockDim.x + threadIdx.x) >> 5;
    int lane = threadIdx.x & 31;
    if (e >= EC) return;
    int h = ei[e], t = ei[EC + e], r = rel[e];
    float ah = __expf(g_lh[e] - g_maxh[h]) / (g_sumh[h] + 1e-16f);
    float at = __expf(g_lt[e] - g_maxt[t]) / (g_sumt[t] + 1e-16f);

    const float4* mh = (const float4*)(g_mWh + (size_t)r * 256);
    const float4* mt = (const float4*)(g_mWt + (size_t)r * 256);
    float4* oh = (float4*)(out + (size_t)h * 256);
    float4* ot = (float4*)(out + (size_t)t * 256);

    float4 v;
    v = mh[lane];
    atomicAdd(oh + lane, make_float4(ah * v.x, ah * v.y, ah * v.z, ah * v.w));
    v = mh[lane + 32];
    atomicAdd(oh + lane + 32, make_float4(ah * v.x, ah * v.y, ah * v.z, ah * v.w));
    v = mt[lane];
    atomicAdd(ot + lane, make_float4(at * v.x, at * v.y, at * v.z, at * v.w));
    v = mt[lane + 32];
    atomicAdd(ot + lane + 32, make_float4(at * v.x, at * v.y, at * v.z, at * v.w));
}

extern "C" void kernel_launch(void* const* d_in, const int* in_sizes, int n_in,
                              void* d_out, int out_size) {
    const float* x_e  = (const float*)d_in[0];
    const float* x_r  = (const float*)d_in[1];
    const int*   ei   = (const int*)d_in[2];
    const int*   rel  = (const int*)d_in[3];
    // d_in[4] = rel_all (unused by reference)
    const float* w_ah = (const float*)d_in[5];
    const float* w_at = (const float*)d_in[6];
    const float* w_ar = (const float*)d_in[7];
    const float* W1   = (const float*)d_in[8];
    const float* b1   = (const float*)d_in[9];
    const float* W2   = (const float*)d_in[10];
    const float* b2   = (const float*)d_in[11];
    const float* Wr   = (const float*)d_in[12];
    const float* br   = (const float*)d_in[13];
    float* out = (float*)d_out;

    k_init_nodes<<<(NE + 255) / 256, 256>>>();
    k_init_out<<<NE, 256>>>(out, br);
    k_node_scores<<<(NE + 7) / 8, 256>>>(x_e, w_ah, w_at);
    k_rel_scores<<<(NR + 7) / 8, 256>>>(x_r, w_ar);
    k_msg<<<NR, 256>>>(x_r, W1, b1, W2, b2);
    k_msgW<<<NR, 256>>>(Wr);
    k_logits<<<(EC + 255) / 256, 256>>>(ei, rel);
    k_sums<<<(EC + 255) / 256, 256>>>(ei);
    k_scatter<<<EC / 8, 256>>>(ei, rel, out);
}

// round 2
// speedup vs baseline: 1.7022x; 1.7022x over previous
#include <cuda_runtime.h>
#include <math_constants.h>

#define NE 100000
#define NR 1000
#define EC 1000000
#define HID 128
#define OUTD 256
#define N2 (2 * NE)
#define SCAN_B 1024
#define SCAN_NB ((N2 + SCAN_B - 1) / SCAN_B)   // 196

// ---- scratch (device globals: allocation-free) ----
__device__ float g_eh[NE];
__device__ float g_et[NE];
__device__ float g_er[NR];
__device__ float g_lh[EC];
__device__ float g_lt[EC];
__device__ float g_msg[NR * HID];
__device__ float g_mWh[NR * OUTD];
__device__ float g_mWt[NR * OUTD];
__device__ int   g_hist[N2];
__device__ int   g_off[N2];
__device__ int   g_cur[N2];
__device__ int   g_idx[2 * EC];
__device__ int   g_part[SCAN_NB];
__device__ int   g_partoff[SCAN_NB];

// ---- zero histograms ----
__global__ void k_zero_hist() {
    int i = blockIdx.x * blockDim.x + threadIdx.x;
    if (i < N2) g_hist[i] = 0;
}

// ---- per-entity attention scores: warp per node ----
__global__ void k_node_scores(const float* __restrict__ xe,
                              const float* __restrict__ wah,
                              const float* __restrict__ wat) {
    int warp = (blockIdx.x * blockDim.x + threadIdx.x) >> 5;
    int lane = threadIdx.x & 31;
    if (warp >= NE) return;
    const float4* row = (const float4*)(xe + (size_t)warp * HID);
    float4 v = row[lane];
    float4 a = ((const float4*)wah)[lane];
    float4 b = ((const float4*)wat)[lane];
    float sh = v.x * a.x + v.y * a.y + v.z * a.z + v.w * a.w;
    float st = v.x * b.x + v.y * b.y + v.z * b.z + v.w * b.w;
    #pragma unroll
    for (int o = 16; o; o >>= 1) {
        sh += __shfl_xor_sync(0xFFFFFFFFu, sh, o);
        st += __shfl_xor_sync(0xFFFFFFFFu, st, o);
    }
    if (lane == 0) { g_eh[warp] = sh; g_et[warp] = st; }
}

// ---- per-relation attention scores: warp per relation ----
__global__ void k_rel_scores(const float* __restrict__ xr,
                             const float* __restrict__ war) {
    int warp = (blockIdx.x * blockDim.x + threadIdx.x) >> 5;
    int lane = threadIdx.x & 31;
    if (warp >= NR) return;
    const float4* row = (const float4*)(xr + (size_t)warp * HID);
    float4 v = row[lane];
    float4 a = ((const float4*)war)[lane];
    float s = v.x * a.x + v.y * a.y + v.z * a.z + v.w * a.w;
    #pragma unroll
    for (int o = 16; o; o >>= 1) s += __shfl_xor_sync(0xFFFFFFFFu, s, o);
    if (lane == 0) g_er[warp] = s;
}

// ---- relation message MLP: msg = x_r + (x_r@W1+b1)@W2+b2 ; block per relation ----
__global__ void k_msg(const float* __restrict__ xr,
                      const float* __restrict__ W1, const float* __restrict__ b1,
                      const float* __restrict__ W2, const float* __restrict__ b2) {
    __shared__ float xs[HID];
    __shared__ float hs[2 * HID];
    int r = blockIdx.x, tid = threadIdx.x;
    if (tid < HID) xs[tid] = xr[(size_t)r * HID + tid];
    __syncthreads();
    float acc = b1[tid];
    #pragma unroll 8
    for (int k = 0; k < HID; k++) acc += xs[k] * W1[k * 256 + tid];
    hs[tid] = acc;
    __syncthreads();
    if (tid < HID) {
        float o = b2[tid];
        #pragma unroll 8
        for (int j = 0; j < 256; j++) o += hs[j] * W2[j * HID + tid];
        g_msg[(size_t)r * HID + tid] = xs[tid] + o;
    }
}

// ---- fold output projection into message tables: block per relation ----
__global__ void k_msgW(const float* __restrict__ Wr) {
    __shared__ float ms[HID];
    int r = blockIdx.x, c = threadIdx.x;
    if (c < HID) ms[c] = g_msg[(size_t)r * HID + c];
    __syncthreads();
    float ah = 0.0f, at = 0.0f;
    #pragma unroll 8
    for (int k = 0; k < HID; k++) {
        float m = ms[k];
        ah += m * Wr[k * 256 + c];
        at += m * Wr[(k + HID) * 256 + c];
    }
    g_mWh[(size_t)r * 256 + c] = ah;
    g_mWt[(size_t)r * 256 + c] = at;
}

// ---- edge pass: logits + degree histogram ----
__global__ void k_logits(const int* __restrict__ ei, const int* __restrict__ rel) {
    int e = blockIdx.x * blockDim.x + threadIdx.x;
    if (e >= EC) return;
    int h = ei[e], t = ei[EC + e], r = rel[e];
    float er = g_er[r];
    float lh = g_eh[h] + er;
    lh = lh > 0.0f ? lh : 0.01f * lh;
    float lt = g_et[t] + er;
    lt = lt > 0.0f ? lt : 0.01f * lt;
    g_lh[e] = lh;
    g_lt[e] = lt;
    atomicAdd(&g_hist[h], 1);
    atomicAdd(&g_hist[NE + t], 1);
}

// ---- scan stage 1: block-level exclusive scan of hist ----
__global__ void k_scan1() {
    __shared__ int sh[SCAN_B];
    int t = threadIdx.x;
    int i = blockIdx.x * SCAN_B + t;
    int v = (i < N2) ? g_hist[i] : 0;
    sh[t] = v;
    __syncthreads();
    #pragma unroll
    for (int d = 1; d < SCAN_B; d <<= 1) {
        int x = (t >= d) ? sh[t - d] : 0;
        __syncthreads();
        sh[t] += x;
        __syncthreads();
    }
    if (i < N2) g_off[i] = sh[t] - v;      // exclusive
    if (t == SCAN_B - 1) g_part[blockIdx.x] = sh[t];
}

// ---- scan stage 2: serial scan of block partials ----
__global__ void k_scan2() {
    if (threadIdx.x == 0) {
        int run = 0;
        for (int b = 0; b < SCAN_NB; b++) {
            g_partoff[b] = run;
            run += g_part[b];
        }
    }
}

// ---- scan stage 3: add block offsets; init cursors ----
__global__ void k_scan3() {
    int i = blockIdx.x * blockDim.x + threadIdx.x;
    if (i < N2) {
        int o = g_off[i] + g_partoff[i / SCAN_B];
        g_off[i] = o;
        g_cur[i] = o;
    }
}

// ---- CSR fill: edge -> slot ----
__global__ void k_fill(const int* __restrict__ ei) {
    int e = blockIdx.x * blockDim.x + threadIdx.x;
    if (e >= EC) return;
    int h = ei[e], t = ei[EC + e];
    int p = atomicAdd(&g_cur[h], 1);
    g_idx[p] = e;
    int q = atomicAdd(&g_cur[NE + t], 1);
    g_idx[q] = e;
}

// ---- per-direction segment softmax + weighted table accumulation ----
__device__ __forceinline__ void seg_accum(int base, int deg, int lane,
                                          const float* __restrict__ lg,
                                          const int* __restrict__ rel,
                                          const float* __restrict__ table,
                                          float4& a0, float4& a1) {
    if (deg <= 0) return;
    // pass 1: max
    float m = -CUDART_INF_F;
    for (int j = lane; j < deg; j += 32) m = fmaxf(m, lg[g_idx[base + j]]);
    #pragma unroll
    for (int o = 16; o; o >>= 1) m = fmaxf(m, __shfl_xor_sync(0xFFFFFFFFu, m, o));
    // pass 2: sum
    float s = 0.0f;
    for (int j = lane; j < deg; j += 32) s += __expf(lg[g_idx[base + j]] - m);
    #pragma unroll
    for (int o = 16; o; o >>= 1) s += __shfl_xor_sync(0xFFFFFFFFu, s, o);
    float inv = 1.0f / (s + 1e-16f);
    // pass 3: accumulate (software pipelined on the uniform chain)
    int e = g_idx[base];
    int r = rel[e];
    float l = lg[e];
    for (int j = 0; j < deg; j++) {
        int e_n = 0, r_n = 0;
        float l_n = 0.0f;
        if (j + 1 < deg) {
            e_n = g_idx[base + j + 1];
            r_n = rel[e_n];
            l_n = lg[e_n];
        }
        float a = __expf(l - m) * inv;
        const float4* tb = (const float4*)(table + (size_t)r * OUTD);
        float4 v0 = tb[lane];
        float4 v1 = tb[lane + 32];
        a0.x += a * v0.x; a0.y += a * v0.y; a0.z += a * v0.z; a0.w += a * v0.w;
        a1.x += a * v1.x; a1.y += a * v1.y; a1.z += a * v1.z; a1.w += a * v1.w;
        e = e_n; r = r_n; l = l_n;
    }
}

// ---- gather: one warp per node, both directions, single row store ----
__global__ void k_gather(const int* __restrict__ rel,
                         const float* __restrict__ br,
                         float* __restrict__ out) {
    int n = (blockIdx.x * blockDim.x + threadIdx.x) >> 5;
    int lane = threadIdx.x & 31;
    if (n >= NE) return;

    float4 a0 = make_float4(0.f, 0.f, 0.f, 0.f);
    float4 a1 = make_float4(0.f, 0.f, 0.f, 0.f);

    seg_accum(g_off[n],      g_hist[n],      lane, g_lh, rel, g_mWh, a0, a1);
    seg_accum(g_off[NE + n], g_hist[NE + n], lane, g_lt, rel, g_mWt, a0, a1);

    float4 b0 = ((const float4*)br)[lane];
    float4 b1 = ((const float4*)br)[lane + 32];
    float4* o = (float4*)(out + (size_t)n * OUTD);
    o[lane]      = make_float4(a0.x + b0.x, a0.y + b0.y, a0.z + b0.z, a0.w + b0.w);
    o[lane + 32] = make_float4(a1.x + b1.x, a1.y + b1.y, a1.z + b1.z, a1.w + b1.w);
}

extern "C" void kernel_launch(void* const* d_in, const int* in_sizes, int n_in,
                              void* d_out, int out_size) {
    const float* x_e  = (const float*)d_in[0];
    const float* x_r  = (const float*)d_in[1];
    const int*   ei   = (const int*)d_in[2];
    const int*   rel  = (const int*)d_in[3];
    // d_in[4] = rel_all (unused by reference)
    const float* w_ah = (const float*)d_in[5];
    const float* w_at = (const float*)d_in[6];
    const float* w_ar = (const float*)d_in[7];
    const float* W1   = (const float*)d_in[8];
    const float* b1   = (const float*)d_in[9];
    const float* W2   = (const float*)d_in[10];
    const float* b2   = (const float*)d_in[11];
    const float* Wr   = (const float*)d_in[12];
    const float* br   = (const float*)d_in[13];
    float* out = (float*)d_out;

    k_zero_hist<<<(N2 + 255) / 256, 256>>>();
    k_node_scores<<<(NE + 7) / 8, 256>>>(x_e, w_ah, w_at);
    k_rel_scores<<<(NR + 7) / 8, 256>>>(x_r, w_ar);
    k_msg<<<NR, 256>>>(x_r, W1, b1, W2, b2);
    k_msgW<<<NR, 256>>>(Wr);
    k_logits<<<(EC + 255) / 256, 256>>>(ei, rel);
    k_scan1<<<SCAN_NB, SCAN_B>>>();
    k_scan2<<<1, 32>>>();
    k_scan3<<<(N2 + 255) / 256, 256>>>();
    k_fill<<<(EC + 255) / 256, 256>>>(ei);
    k_gather<<<(NE + 7) / 8, 256>>>(rel, br, out);
}

// round 3
// speedup vs baseline: 2.0966x; 1.2317x over previous
#include <cuda_runtime.h>
#include <cuda_fp16.h>
#include <math_constants.h>

#define NE 100000
#define NR 1000
#define EC 1000000
#define HID 128
#define OUTD 256
#define N2 (2 * NE)
#define SCAN_B 1024
#define SCAN_NB ((N2 + SCAN_B - 1) / SCAN_B)   // 196
#define RT 8                                    // relations per MLP block

// ---- scratch (device globals: allocation-free) ----
__device__ float  g_eh[NE];
__device__ float  g_et[NE];
__device__ float  g_er[NR];
__device__ float  g_lh[EC];
__device__ float  g_lt[EC];
__device__ __half g_tWh[NR * OUTD];
__device__ __half g_tWt[NR * OUTD];
__device__ int    g_hist[N2];
__device__ int    g_off[N2];
__device__ int    g_cur[N2];
__device__ int    g_idx[2 * EC];
__device__ int    g_part[SCAN_NB];
__device__ int    g_partoff[SCAN_NB];

// ---- zero histograms ----
__global__ void k_zero_hist() {
    int i = blockIdx.x * blockDim.x + threadIdx.x;
    if (i < N2) g_hist[i] = 0;
}

// ---- per-entity attention scores: warp per node ----
__global__ void k_node_scores(const float* __restrict__ xe,
                              const float* __restrict__ wah,
                              const float* __restrict__ wat) {
    int warp = (blockIdx.x * blockDim.x + threadIdx.x) >> 5;
    int lane = threadIdx.x & 31;
    if (warp >= NE) return;
    const float4* row = (const float4*)(xe + (size_t)warp * HID);
    float4 v = row[lane];
    float4 a = ((const float4*)wah)[lane];
    float4 b = ((const float4*)wat)[lane];
    float sh = v.x * a.x + v.y * a.y + v.z * a.z + v.w * a.w;
    float st = v.x * b.x + v.y * b.y + v.z * b.z + v.w * b.w;
    #pragma unroll
    for (int o = 16; o; o >>= 1) {
        sh += __shfl_xor_sync(0xFFFFFFFFu, sh, o);
        st += __shfl_xor_sync(0xFFFFFFFFu, st, o);
    }
    if (lane == 0) { g_eh[warp] = sh; g_et[warp] = st; }
}

// ---- per-relation attention scores: warp per relation ----
__global__ void k_rel_scores(const float* __restrict__ xr,
                             const float* __restrict__ war) {
    int warp = (blockIdx.x * blockDim.x + threadIdx.x) >> 5;
    int lane = threadIdx.x & 31;
    if (warp >= NR) return;
    const float4* row = (const float4*)(xr + (size_t)warp * HID);
    float4 v = row[lane];
    float4 a = ((const float4*)war)[lane];
    float s = v.x * a.x + v.y * a.y + v.z * a.z + v.w * a.w;
    #pragma unroll
    for (int o = 16; o; o >>= 1) s += __shfl_xor_sync(0xFFFFFFFFu, s, o);
    if (lane == 0) g_er[warp] = s;
}

// ---- fused relation MLP + W_r fold: 8 relations per block ----
// msg = x_r + relu_less( (x_r@W1+b1)@W2+b2 ); tables = half(msg @ Wr[0:128|128:256])
__global__ void k_mlp(const float* __restrict__ xr,
                      const float* __restrict__ W1, const float* __restrict__ b1,
                      const float* __restrict__ W2, const float* __restrict__ b2,
                      const float* __restrict__ Wr) {
    __shared__ float xs[RT][HID];        // x_r rows, later msg rows
    __shared__ float hs[RT][2 * HID];    // hidden layer
    int r0 = blockIdx.x * RT;
    int tid = threadIdx.x;               // 256 threads

    for (int i = tid; i < RT * HID; i += 256) {
        int rr = i >> 7, c = i & 127;
        xs[rr][c] = xr[(size_t)(r0 + rr) * HID + c];
    }
    __syncthreads();

    // layer 1: hs[i][tid] = b1[tid] + sum_k xs[i][k] * W1[k*256+tid]
    {
        float acc[RT];
        float bb = b1[tid];
        #pragma unroll
        for (int i = 0; i < RT; i++) acc[i] = bb;
        for (int k = 0; k < HID; k++) {
            float w = W1[k * 256 + tid];
            #pragma unroll
            for (int i = 0; i < RT; i++) acc[i] += xs[i][k] * w;
        }
        #pragma unroll
        for (int i = 0; i < RT; i++) hs[i][tid] = acc[i];
    }
    __syncthreads();

    // layer 2 + residual: xs[i][c] += b2[c] + sum_j hs[i][j] * W2[j*128+c]
    {
        int c = tid & 127;
        int g = tid >> 7;                  // 0 or 1, each handles 4 relations
        float acc[RT / 2];
        #pragma unroll
        for (int i = 0; i < RT / 2; i++) acc[i] = 0.0f;
        for (int j = 0; j < 2 * HID; j++) {
            float w = W2[j * HID + c];
            #pragma unroll
            for (int i = 0; i < RT / 2; i++) acc[i] += hs[g * 4 + i][j] * w;
        }
        float bb = b2[c];
        #pragma unroll
        for (int i = 0; i < RT / 2; i++) xs[g * 4 + i][c] += bb + acc[i];
    }
    __syncthreads();

    // layer 3: tables. ah[i] = sum_k msg[i][k]*Wr[k*256+tid]; at with k+128
    {
        float ah[RT], at[RT];
        #pragma unroll
        for (int i = 0; i < RT; i++) { ah[i] = 0.0f; at[i] = 0.0f; }
        for (int k = 0; k < HID; k++) {
            float wh = Wr[k * 256 + tid];
            float wt = Wr[(k + HID) * 256 + tid];
            #pragma unroll
            for (int i = 0; i < RT; i++) {
                float m = xs[i][k];
                ah[i] += m * wh;
                at[i] += m * wt;
            }
        }
        #pragma unroll
        for (int i = 0; i < RT; i++) {
            g_tWh[(size_t)(r0 + i) * OUTD + tid] = __float2half(ah[i]);
            g_tWt[(size_t)(r0 + i) * OUTD + tid] = __float2half(at[i]);
        }
    }
}

// ---- edge pass: logits + degree histogram ----
__global__ void k_logits(const int* __restrict__ ei, const int* __restrict__ rel) {
    int e = blockIdx.x * blockDim.x + threadIdx.x;
    if (e >= EC) return;
    int h = ei[e], t = ei[EC + e], r = rel[e];
    float er = g_er[r];
    float lh = g_eh[h] + er;
    lh = lh > 0.0f ? lh : 0.01f * lh;
    float lt = g_et[t] + er;
    lt = lt > 0.0f ? lt : 0.01f * lt;
    g_lh[e] = lh;
    g_lt[e] = lt;
    atomicAdd(&g_hist[h], 1);
    atomicAdd(&g_hist[NE + t], 1);
}

// ---- scan stage 1 ----
__global__ void k_scan1() {
    __shared__ int sh[SCAN_B];
    int t = threadIdx.x;
    int i = blockIdx.x * SCAN_B + t;
    int v = (i < N2) ? g_hist[i] : 0;
    sh[t] = v;
    __syncthreads();
    #pragma unroll
    for (int d = 1; d < SCAN_B; d <<= 1) {
        int x = (t >= d) ? sh[t - d] : 0;
        __syncthreads();
        sh[t] += x;
        __syncthreads();
    }
    if (i < N2) g_off[i] = sh[t] - v;
    if (t == SCAN_B - 1) g_part[blockIdx.x] = sh[t];
}

// ---- scan stage 2 ----
__global__ void k_scan2() {
    if (threadIdx.x == 0) {
        int run = 0;
        for (int b = 0; b < SCAN_NB; b++) {
            g_partoff[b] = run;
            run += g_part[b];
        }
    }
}

// ---- scan stage 3 ----
__global__ void k_scan3() {
    int i = blockIdx.x * blockDim.x + threadIdx.x;
    if (i < N2) {
        int o = g_off[i] + g_partoff[i / SCAN_B];
        g_off[i] = o;
        g_cur[i] = o;
    }
}

// ---- CSR fill ----
__global__ void k_fill(const int* __restrict__ ei) {
    int e = blockIdx.x * blockDim.x + threadIdx.x;
    if (e >= EC) return;
    int h = ei[e], t = ei[EC + e];
    int p = atomicAdd(&g_cur[h], 1);
    g_idx[p] = e;
    int q = atomicAdd(&g_cur[NE + t], 1);
    g_idx[q] = e;
}

// ---- fma 8 halfs into fp32 accumulators ----
__device__ __forceinline__ void fma8(float* acc, uint4 p, float a) {
    __half2* h = reinterpret_cast<__half2*>(&p);
    #pragma unroll
    for (int q = 0; q < 4; q++) {
        float2 f = __half22float2(h[q]);
        acc[2 * q]     += a * f.x;
        acc[2 * q + 1] += a * f.y;
    }
}

// ---- segment softmax + weighted half-table accumulation ----
__device__ __forceinline__ void seg_accum(int base, int deg, int lane,
                                          const float* __restrict__ lg,
                                          const int* __restrict__ rel,
                                          const __half* __restrict__ table,
                                          float* acc) {
    if (deg <= 0) return;
    if (deg <= 32) {
        float l = -CUDART_INF_F;
        int r = 0;
        if (lane < deg) {
            int e = g_idx[base + lane];
            l = lg[e];
            r = rel[e];
        }
        float m = l;
        #pragma unroll
        for (int o = 16; o; o >>= 1) m = fmaxf(m, __shfl_xor_sync(0xFFFFFFFFu, m, o));
        float z = (lane < deg) ? __expf(l - m) : 0.0f;
        float s = z;
        #pragma unroll
        for (int o = 16; o; o >>= 1) s += __shfl_xor_sync(0xFFFFFFFFu, s, o);
        float a_own = z / (s + 1e-16f);
        for (int j = 0; j < deg; j++) {
            float a = __shfl_sync(0xFFFFFFFFu, a_own, j);
            int rj  = __shfl_sync(0xFFFFFFFFu, r, j);
            uint4 p = ((const uint4*)(table + (size_t)rj * OUTD))[lane];
            fma8(acc, p, a);
        }
    } else {
        float m = -CUDART_INF_F;
        for (int j = lane; j < deg; j += 32) m = fmaxf(m, lg[g_idx[base + j]]);
        #pragma unroll
        for (int o = 16; o; o >>= 1) m = fmaxf(m, __shfl_xor_sync(0xFFFFFFFFu, m, o));
        float s = 0.0f;
        for (int j = lane; j < deg; j += 32) s += __expf(lg[g_idx[base + j]] - m);
        #pragma unroll
        for (int o = 16; o; o >>= 1) s += __shfl_xor_sync(0xFFFFFFFFu, s, o);
        float inv = 1.0f / (s + 1e-16f);
        for (int c0 = 0; c0 < deg; c0 += 32) {
            int j = c0 + lane;
            float a_own = 0.0f;
            int r = 0;
            if (j < deg) {
                int e = g_idx[base + j];
                a_own = __expf(lg[e] - m) * inv;
                r = rel[e];
            }
            int cnt = min(32, deg - c0);
            for (int jj = 0; jj < cnt; jj++) {
                float a = __shfl_sync(0xFFFFFFFFu, a_own, jj);
                int rj  = __shfl_sync(0xFFFFFFFFu, r, jj);
                uint4 p = ((const uint4*)(table + (size_t)rj * OUTD))[lane];
                fma8(acc, p, a);
            }
        }
    }
}

// ---- gather: one warp per node, both directions, single row store ----
__global__ void k_gather(const int* __restrict__ rel,
                         const float* __restrict__ br,
                         float* __restrict__ out) {
    int n = (blockIdx.x * blockDim.x + threadIdx.x) >> 5;
    int lane = threadIdx.x & 31;
    if (n >= NE) return;

    float acc[8];
    #pragma unroll
    for (int q = 0; q < 8; q++) acc[q] = 0.0f;

    seg_accum(g_off[n],      g_hist[n],      lane, g_lh, rel, g_tWh, acc);
    seg_accum(g_off[NE + n], g_hist[NE + n], lane, g_lt, rel, g_tWt, acc);

    float4 b0 = ((const float4*)(br + lane * 8))[0];
    float4 b1 = ((const float4*)(br + lane * 8))[1];
    float4* o = (float4*)(out + (size_t)n * OUTD + lane * 8);
    o[0] = make_float4(acc[0] + b0.x, acc[1] + b0.y, acc[2] + b0.z, acc[3] + b0.w);
    o[1] = make_float4(acc[4] + b1.x, acc[5] + b1.y, acc[6] + b1.z, acc[7] + b1.w);
}

extern "C" void kernel_launch(void* const* d_in, const int* in_sizes, int n_in,
                              void* d_out, int out_size) {
    const float* x_e  = (const float*)d_in[0];
    const float* x_r  = (const float*)d_in[1];
    const int*   ei   = (const int*)d_in[2];
    const int*   rel  = (const int*)d_in[3];
    const float* w_ah = (const float*)d_in[5];
    const float* w_at = (const float*)d_in[6];
    const float* w_ar = (const float*)d_in[7];
    const float* W1   = (const float*)d_in[8];
    const float* b1   = (const float*)d_in[9];
    const float* W2   = (const float*)d_in[10];
    const float* b2   = (const float*)d_in[11];
    const float* Wr   = (const float*)d_in[12];
    const float* br   = (const float*)d_in[13];
    float* out = (float*)d_out;

    k_zero_hist<<<(N2 + 255) / 256, 256>>>();
    k_node_scores<<<(NE + 7) / 8, 256>>>(x_e, w_ah, w_at);
    k_rel_scores<<<(NR + 7) / 8, 256>>>(x_r, w_ar);
    k_mlp<<<NR / RT, 256>>>(x_r, W1, b1, W2, b2, Wr);
    k_logits<<<(EC + 255) / 256, 256>>>(ei, rel);
    k_scan1<<<SCAN_NB, SCAN_B>>>();
    k_scan2<<<1, 32>>>();
    k_scan3<<<(N2 + 255) / 256, 256>>>();
    k_fill<<<(EC + 255) / 256, 256>>>(ei);
    k_gather<<<(NE + 7) / 8, 256>>>(rel, br, out);
}